// round 13
// baseline (speedup 1.0000x reference)
#include <cuda_runtime.h>
#include <cuda_fp16.h>
#include <cstdint>
#include <cstddef>

// ---------------------------------------------------------------------------
// GroupedQueryAttention: B=2, S=2048, D_IN=2048, 32 heads x 64, 8 KV groups
// d_out: out [2,2048,2048] | keys [2,8,2048,64] | values [2,8,2048,64]
// fp16 mma.sync m16n8k16 (fp32 accum); legacy HMMA measured at its ~310 TF/s
// hardware ceiling.  R13 = R10 exactly, except the attention K/V pipeline is
// triple-buffered so the bottom per-tile __syncthreads is removed (the top
// barrier of tile kt already proves all warps finished tile kt-1, whose
// buffer is the prefetch target).  Compute body untouched.
// ---------------------------------------------------------------------------

namespace {
constexpr int kB    = 2;
constexpr int kS    = 2048;
constexpr int kDin  = 2048;
constexpr int kDout = 2048;
constexpr int kNH   = 32;
constexpr int kNKV  = 8;
constexpr int kHD   = 64;
constexpr int kM    = kB * kS;       // 4096
constexpr int kDkv  = kNKV * kHD;    // 512
constexpr int kNQKV = kDout + 2 * kDkv;   // 3072
constexpr float kQScale = 0.125f * 1.4426950408889634f;   // 1/sqrt(64)*log2(e)
constexpr uint32_t kOnesH2 = 0x3C003C00u;                 // half2(1,1)
}

// Scratch (device globals: no allocation allowed)
__device__ __half g_Qh  [(size_t)kM * kDout];      // pre-scaled fp16 Q
__device__ __half g_ctxh[(size_t)kM * kDout];      // fp16 ctx
__device__ __half g_xH  [(size_t)kM * kDin];
__device__ __half g_wH  [(size_t)kNQKV * kDin];    // [Wq;Wk;Wv] fp16
__device__ __half g_woH [(size_t)kDin * kDout];
__device__ __half g_kH  [(size_t)kB * kNKV * kS * kHD];
__device__ __half g_vH  [(size_t)kB * kNKV * kS * kHD];

// ------------------------- helpers -----------------------------------------
__device__ __forceinline__ uint32_t smem_u32(const void* p) {
    uint32_t a;
    asm("{ .reg .u64 t; cvta.to.shared.u64 t, %1; cvt.u32.u64 %0, t; }" : "=r"(a) : "l"(p));
    return a;
}
__device__ __forceinline__ uint32_t pack_h2(float lo, float hi) {
    uint32_t r;
    asm("cvt.rn.f16x2.f32 %0, %1, %2;" : "=r"(r) : "f"(hi), "f"(lo));
    return r;
}
__device__ __forceinline__ uint32_t h2exp2(uint32_t x) {
    uint32_t r;
    asm("ex2.approx.f16x2 %0, %1;" : "=r"(r) : "r"(x));
    return r;
}
__device__ __forceinline__ float fexp2(float x) {
    float r;
    asm("ex2.approx.f32 %0, %1;" : "=f"(r) : "f"(x));
    return r;
}
// Pure register op: NOT volatile — lets ptxas schedule HMMA freely.
__device__ __forceinline__ void mma_f16(float& c0, float& c1, float& c2, float& c3,
                                        uint32_t a0, uint32_t a1, uint32_t a2, uint32_t a3,
                                        uint32_t b0, uint32_t b1) {
    asm("mma.sync.aligned.m16n8k16.row.col.f32.f16.f16.f32 "
        "{%0,%1,%2,%3}, {%4,%5,%6,%7}, {%8,%9}, {%0,%1,%2,%3};"
        : "+f"(c0), "+f"(c1), "+f"(c2), "+f"(c3)
        : "r"(a0), "r"(a1), "r"(a2), "r"(a3), "r"(b0), "r"(b1));
}
#define LDMX4(r, addr)                                                        \
    asm volatile("ldmatrix.sync.aligned.m8n8.x4.shared.b16 {%0,%1,%2,%3}, [%4];" \
        : "=r"((r)[0]), "=r"((r)[1]), "=r"((r)[2]), "=r"((r)[3]) : "r"(addr))
#define LDMX4T(r, addr)                                                       \
    asm volatile("ldmatrix.sync.aligned.m8n8.x4.trans.shared.b16 {%0,%1,%2,%3}, [%4];" \
        : "=r"((r)[0]), "=r"((r)[1]), "=r"((r)[2]), "=r"((r)[3]) : "r"(addr))
__device__ __forceinline__ void cp_async16(uint32_t dst, const void* src) {
    asm volatile("cp.async.cg.shared.global [%0], [%1], 16;" :: "r"(dst), "l"(src));
}
#define CP_COMMIT() asm volatile("cp.async.commit_group;" ::: "memory")
#define CP_WAIT(n)  asm volatile("cp.async.wait_group %0;" :: "n"(n) : "memory")

// ---------------------------------------------------------------------------
// Single-pass fp32 -> fp16 conversion of x, [Wq;Wk;Wv] and Wo
// ---------------------------------------------------------------------------
namespace {
constexpr int N4X = kM * kDin / 4;
constexpr int N4Q = kDout * kDin / 4;
constexpr int N4K = kDkv * kDin / 4;
constexpr int N4O = kDin * kDout / 4;
constexpr int N4T = N4X + N4Q + 2 * N4K + N4O;
}

__global__ __launch_bounds__(256)
void cvt_all(const float4* __restrict__ x,  const float4* __restrict__ wq,
             const float4* __restrict__ wk, const float4* __restrict__ wv,
             const float4* __restrict__ wo)
{
    uint2* xH  = (uint2*)g_xH;
    uint2* wH  = (uint2*)g_wH;
    uint2* woH = (uint2*)g_woH;
    int i = blockIdx.x * blockDim.x + threadIdx.x;
    const int stride = gridDim.x * blockDim.x;
    for (; i < N4T; i += stride) {
        float4 v;
        uint2* dst;
        if (i < N4X)                       { v = x[i];                       dst = xH + i; }
        else if (i < N4X + N4Q)            { int j = i - N4X;                v = wq[j]; dst = wH + j; }
        else if (i < N4X + N4Q + N4K)      { int j = i - N4X - N4Q;          v = wk[j]; dst = wH + N4Q + j; }
        else if (i < N4X + N4Q + 2 * N4K)  { int j = i - N4X - N4Q - N4K;    v = wv[j]; dst = wH + N4Q + N4K + j; }
        else                               { int j = i - N4X - N4Q - 2*N4K;  v = wo[j]; dst = woH + j; }
        uint2 o;
        o.x = pack_h2(v.x, v.y);
        o.y = pack_h2(v.z, v.w);
        *dst = o;
    }
}

// ---------------------------------------------------------------------------
// GEMM: BM=BN=128, BK=64, 256 threads (8 warps, warp tile 32x64),
// 3-stage cp.async pipeline, one barrier per chunk, grouped raster.
// FUSED: 0 = plain fp32 C (O-proj), 1 = QKV fused epilogue.
// ---------------------------------------------------------------------------
namespace {
constexpr int BM = 128, BN = 128, BK = 64, STR = 72;      // STR in halfs
constexpr int kStageH   = (BM + BN) * STR;                // 18432 halfs
constexpr int kGemmSmem = 3 * kStageH * 2;                // 110592 B
}

template <int FUSED>
__global__ __launch_bounds__(256, 2)
void gemm_f16(const __half* __restrict__ A, const __half* __restrict__ Bw,
              float* __restrict__ C, float* __restrict__ keys,
              float* __restrict__ values, int M, int N, int K)
{
    extern __shared__ __half smh[];
    const uint32_t smBase = smem_u32(smh);

    const int t    = threadIdx.x;
    const int lane = t & 31;
    const int wid  = t >> 5;
    const int wm   = (wid & 3) * 32;
    const int wn   = (wid >> 2) * 64;

    // grouped raster for L2 locality
    const int nbn = gridDim.x, nbm = gridDim.y;
    const int bid = blockIdx.y * nbn + blockIdx.x;
    const int ning = 8 * nbn;
    const int gid  = bid / ning;
    const int fm   = gid * 8;
    const int gsz  = min(8, nbm - fm);
    const int r    = bid % ning;
    const int rowBase = (fm + r % gsz) * BM;
    const int colBase = (r / gsz) * BN;

    float acc[2][8][4] = {};

    auto load_tile = [&](int kt, int st) {
        const __half* Ag = A  + (size_t)rowBase * K + kt * BK;
        const __half* Bg = Bw + (size_t)colBase * K + kt * BK;
        const uint32_t dst = smBase + st * kStageH * 2;
#pragma unroll
        for (int i = 0; i < 4; i++) {
            const int v = t + i * 256;
            const int rr = v >> 3, c8 = (v & 7) * 8;
            cp_async16(dst + (rr * STR + c8) * 2, Ag + (size_t)rr * K + c8);
        }
#pragma unroll
        for (int i = 0; i < 4; i++) {
            const int v = t + i * 256;
            const int rr = v >> 3, c8 = (v & 7) * 8;
            cp_async16(dst + (BM * STR + rr * STR + c8) * 2, Bg + (size_t)rr * K + c8);
        }
        CP_COMMIT();
    };

    const uint32_t aOff = ((wm + (lane & 15)) * STR + (lane >> 4) * 8) * 2;
    const uint32_t bOff = ((wn + ((lane >> 4) & 1) * 8 + (lane & 7)) * STR
                           + ((lane >> 3) & 1) * 8) * 2;

    const int NC = K / BK;
    load_tile(0, 0);
    load_tile(1, 1);

    int st = 0;
    for (int c = 0; c < NC; c++) {
        if (c + 1 < NC) { CP_WAIT(1); } else { CP_WAIT(0); }
        __syncthreads();
        if (c + 2 < NC) {
            int st2 = st + 2; if (st2 >= 3) st2 -= 3;
            load_tile(c + 2, st2);
        }

        const uint32_t ba = smBase + st * kStageH * 2;
        const uint32_t bb = ba + BM * STR * 2;
#pragma unroll
        for (int ks = 0; ks < 4; ks++) {
            uint32_t af[2][4];
            LDMX4(af[0], ba + aOff + (ks * 16) * 2);
            LDMX4(af[1], ba + aOff + (16 * STR + ks * 16) * 2);
#pragma unroll
            for (int p = 0; p < 4; p++) {
                uint32_t bf[4];
                LDMX4(bf, bb + bOff + (p * 16 * STR + ks * 16) * 2);
                mma_f16(acc[0][2*p][0], acc[0][2*p][1], acc[0][2*p][2], acc[0][2*p][3],
                        af[0][0], af[0][1], af[0][2], af[0][3], bf[0], bf[1]);
                mma_f16(acc[1][2*p][0], acc[1][2*p][1], acc[1][2*p][2], acc[1][2*p][3],
                        af[1][0], af[1][1], af[1][2], af[1][3], bf[0], bf[1]);
                mma_f16(acc[0][2*p+1][0], acc[0][2*p+1][1], acc[0][2*p+1][2], acc[0][2*p+1][3],
                        af[0][0], af[0][1], af[0][2], af[0][3], bf[2], bf[3]);
                mma_f16(acc[1][2*p+1][0], acc[1][2*p+1][1], acc[1][2*p+1][2], acc[1][2*p+1][3],
                        af[1][0], af[1][1], af[1][2], af[1][3], bf[2], bf[3]);
            }
        }
        if (++st == 3) st = 0;
    }

    // ---- epilogue
    if (FUSED == 0) {
#pragma unroll
        for (int mt = 0; mt < 2; mt++)
#pragma unroll
        for (int nt = 0; nt < 8; nt++) {
            const int row0 = rowBase + wm + mt * 16 + (lane >> 2);
            const int col  = colBase + wn + nt * 8 + 2 * (lane & 3);
            *(float2*)&C[(size_t)row0 * N + col] =
                make_float2(acc[mt][nt][0], acc[mt][nt][1]);
            *(float2*)&C[(size_t)(row0 + 8) * N + col] =
                make_float2(acc[mt][nt][2], acc[mt][nt][3]);
        }
    } else if (colBase < kDout) {
#pragma unroll
        for (int mt = 0; mt < 2; mt++)
#pragma unroll
        for (int nt = 0; nt < 8; nt++) {
            const int row0 = rowBase + wm + mt * 16 + (lane >> 2);
            const int col  = colBase + wn + nt * 8 + 2 * (lane & 3);
            *(uint32_t*)&g_Qh[(size_t)row0 * kDout + col] =
                pack_h2(kQScale * acc[mt][nt][0], kQScale * acc[mt][nt][1]);
            *(uint32_t*)&g_Qh[(size_t)(row0 + 8) * kDout + col] =
                pack_h2(kQScale * acc[mt][nt][2], kQScale * acc[mt][nt][3]);
        }
    } else {
        const bool isK = colBase < kDout + kDkv;
        float*  d32 = isK ? keys : values;
        __half* d16 = isK ? g_kH : g_vH;
        const int nBase = colBase - (isK ? kDout : (kDout + kDkv));
#pragma unroll
        for (int mt = 0; mt < 2; mt++)
#pragma unroll
        for (int nt = 0; nt < 8; nt++) {
            const int row0 = rowBase + wm + mt * 16 + (lane >> 2);
            const int nloc = nBase + wn + nt * 8 + 2 * (lane & 3);
            const int g = nloc >> 6, d = nloc & 63;
            {
                const int bb2 = row0 >> 11, ss = row0 & (kS - 1);
                const size_t o = ((((size_t)bb2 * kNKV + g) * kS + ss) << 6) + d;
                *(float2*)&d32[o] = make_float2(acc[mt][nt][0], acc[mt][nt][1]);
                *(uint32_t*)&d16[o] = pack_h2(acc[mt][nt][0], acc[mt][nt][1]);
            }
            {
                const int r1 = row0 + 8;
                const int bb2 = r1 >> 11, ss = r1 & (kS - 1);
                const size_t o = ((((size_t)bb2 * kNKV + g) * kS + ss) << 6) + d;
                *(float2*)&d32[o] = make_float2(acc[mt][nt][2], acc[mt][nt][3]);
                *(uint32_t*)&d16[o] = pack_h2(acc[mt][nt][2], acc[mt][nt][3]);
            }
        }
    }
}

// ---------------------------------------------------------------------------
// Causal GQA flash attention, fp16 mma (m16n8k16).
// 8 warps x 16 q-rows = 128 rows/block; 64-key tiles; grid = (S/128, B*NH),
// x reversed so heavy CTAs launch first.  f16x2 exp, ones-mma row sums.
// R13: triple-buffered K/V tiles — ONE barrier per tile (prefetch for kt+2
// targets tile kt-1's buffer, proven free by the top barrier of tile kt).
// Compute body identical to R10.
// ---------------------------------------------------------------------------
namespace {
constexpr int kAStr = 72;
constexpr int kAttBufH = 2 * 64 * kAStr;                   // 9216 halfs/buffer
constexpr int kAttSmem = 3 * kAttBufH * 2;                 // 55296 B
}

__global__ __launch_bounds__(256, 2)
void attn_mma(const __half* __restrict__ Qh, const __half* __restrict__ KH,
              const __half* __restrict__ VH, __half* __restrict__ ctx)
{
    extern __shared__ __half smh[];
    const uint32_t smBase = smem_u32(smh);

    const int t    = threadIdx.x;
    const int lane = t & 31;
    const int wid  = t >> 5;
    const int bh = blockIdx.y;
    const int b  = bh >> 5;
    const int h  = bh & 31;
    const int g  = h >> 2;
    const int qx = (int)gridDim.x - 1 - (int)blockIdx.x;
    const int qb = qx * 128;
    const int wm = wid * 16;

    // ---- stage Q (fp16, pre-scaled) into buffer 0 region, then to fragments
    const __half* qg = Qh + ((size_t)(b * kS + qb)) * kDout + h * kHD;
#pragma unroll
    for (int i = 0; i < 4; i++) {
        const int v = t + i * 256;
        const int rr = v >> 3, c8 = (v & 7) * 8;
        *(uint4*)&smh[rr * kAStr + c8] = *(const uint4*)&qg[(size_t)rr * kDout + c8];
    }
    __syncthreads();
    uint32_t qf[4][4];
    {
        const uint32_t qOff = smBase + ((wm + (lane & 15)) * kAStr + (lane >> 4) * 8) * 2;
#pragma unroll
        for (int ks = 0; ks < 4; ks++) LDMX4(qf[ks], qOff + (ks * 16) * 2);
    }
    __syncthreads();

    float oacc[8][4] = {};
    float m0 = -1e30f, m1 = -1e30f, l0 = 0.f, l1 = 0.f;

    const __half* kg = KH + ((size_t)(b * kNKV + g)) * kS * kHD;
    const __half* vg = VH + ((size_t)(b * kNKV + g)) * kS * kHD;

    auto load_tile = [&](int kt, int buf) {
        const uint32_t dstK = smBase + buf * kAttBufH * 2;
        const uint32_t dstV = dstK + 64 * kAStr * 2;
#pragma unroll
        for (int i = 0; i < 2; i++) {
            const int v = t + i * 256;
            const int key = v >> 3, c8 = (v & 7) * 8;
            cp_async16(dstK + (key * kAStr + c8) * 2, kg + (size_t)(kt * 64 + key) * kHD + c8);
        }
#pragma unroll
        for (int i = 0; i < 2; i++) {
            const int v = t + i * 256;
            const int key = v >> 3, c8 = (v & 7) * 8;
            cp_async16(dstV + (key * kAStr + c8) * 2, vg + (size_t)(kt * 64 + key) * kHD + c8);
        }
        CP_COMMIT();
    };

    const uint32_t kOffRel =
        ((((lane >> 4) & 1) * 8 + (lane & 7)) * kAStr + ((lane >> 3) & 1) * 8) * 2;
    const uint32_t vOffRel =
        ((((lane >> 3) & 1) * 8 + (lane & 7)) * kAStr + ((lane >> 4) & 1) * 8) * 2;

    const int ntk = qx * 2 + 2;
    load_tile(0, 0);
    load_tile(1, 1);

    int buf = 0;    // buffer of tile kt
    for (int kt = 0; kt < ntk; kt++) {
        if (kt + 1 < ntk) { CP_WAIT(1); } else { CP_WAIT(0); }
        __syncthreads();                       // tile kt ready; kt-1 done by all
        if (kt + 2 < ntk) {
            int b2 = buf + 2; if (b2 >= 3) b2 -= 3;   // = buffer of tile kt-1
            load_tile(kt + 2, b2);
        }

        const int rmax = qb + wm + 15;
        if (kt * 64 <= rmax) {                 // warp-uniform tile skip
            const uint32_t kBase = smBase + buf * kAttBufH * 2 + kOffRel;
            const uint32_t vBase = smBase + buf * kAttBufH * 2 + 64 * kAStr * 2 + vOffRel;

            float sacc[8][4] = {};
#pragma unroll
            for (int ks = 0; ks < 4; ks++) {
#pragma unroll
                for (int p = 0; p < 4; p++) {
                    uint32_t bf[4];
                    LDMX4(bf, kBase + (p * 16 * kAStr + ks * 16) * 2);
                    mma_f16(sacc[2*p][0], sacc[2*p][1], sacc[2*p][2], sacc[2*p][3],
                            qf[ks][0], qf[ks][1], qf[ks][2], qf[ks][3], bf[0], bf[1]);
                    mma_f16(sacc[2*p+1][0], sacc[2*p+1][1], sacc[2*p+1][2], sacc[2*p+1][3],
                            qf[ks][0], qf[ks][1], qf[ks][2], qf[ks][3], bf[2], bf[3]);
                }
            }

            const int r0 = qb + wm + (lane >> 2);
            const int r1 = r0 + 8;
            if (kt * 64 + 63 > qb + wm) {
#pragma unroll
                for (int nt = 0; nt < 8; nt++) {
                    const int c0 = kt * 64 + nt * 8 + 2 * (lane & 3);
                    if (c0     > r0) sacc[nt][0] = -1e30f;
                    if (c0 + 1 > r0) sacc[nt][1] = -1e30f;
                    if (c0     > r1) sacc[nt][2] = -1e30f;
                    if (c0 + 1 > r1) sacc[nt][3] = -1e30f;
                }
            }

            float t0 = -1e30f, t1 = -1e30f;
#pragma unroll
            for (int nt = 0; nt < 8; nt++) {
                t0 = fmaxf(t0, fmaxf(sacc[nt][0], sacc[nt][1]));
                t1 = fmaxf(t1, fmaxf(sacc[nt][2], sacc[nt][3]));
            }
            t0 = fmaxf(t0, __shfl_xor_sync(0xFFFFFFFFu, t0, 1));
            t0 = fmaxf(t0, __shfl_xor_sync(0xFFFFFFFFu, t0, 2));
            t1 = fmaxf(t1, __shfl_xor_sync(0xFFFFFFFFu, t1, 1));
            t1 = fmaxf(t1, __shfl_xor_sync(0xFFFFFFFFu, t1, 2));
            const float mn0 = fmaxf(m0, t0);
            const float mn1 = fmaxf(m1, t1);
            const float corr0 = fexp2(m0 - mn0);
            const float corr1 = fexp2(m1 - mn1);
            m0 = mn0; m1 = mn1;

            uint32_t p01[8], p23[8];
#pragma unroll
            for (int nt = 0; nt < 8; nt++) {
                p01[nt] = h2exp2(pack_h2(sacc[nt][0] - mn0, sacc[nt][1] - mn0));
                p23[nt] = h2exp2(pack_h2(sacc[nt][2] - mn1, sacc[nt][3] - mn1));
            }

#pragma unroll
            for (int nt = 0; nt < 8; nt++) {
                oacc[nt][0] *= corr0; oacc[nt][1] *= corr0;
                oacc[nt][2] *= corr1; oacc[nt][3] *= corr1;
            }

            float lacc[4] = {};
#pragma unroll
            for (int ks = 0; ks < 4; ks++) {
                const uint32_t a0 = p01[2*ks];
                const uint32_t a1 = p23[2*ks];
                const uint32_t a2 = p01[2*ks+1];
                const uint32_t a3 = p23[2*ks+1];
                mma_f16(lacc[0], lacc[1], lacc[2], lacc[3],
                        a0, a1, a2, a3, kOnesH2, kOnesH2);
#pragma unroll
                for (int p = 0; p < 4; p++) {
                    uint32_t vf[4];
                    LDMX4T(vf, vBase + (ks * 16 * kAStr + p * 16) * 2);
                    mma_f16(oacc[2*p][0], oacc[2*p][1], oacc[2*p][2], oacc[2*p][3],
                            a0, a1, a2, a3, vf[0], vf[1]);
                    mma_f16(oacc[2*p+1][0], oacc[2*p+1][1], oacc[2*p+1][2], oacc[2*p+1][3],
                            a0, a1, a2, a3, vf[2], vf[3]);
                }
            }
            l0 = l0 * corr0 + lacc[0];
            l1 = l1 * corr1 + lacc[2];
        }
        if (++buf == 3) buf = 0;
    }

    const float inv0 = 1.f / l0;
    const float inv1 = 1.f / l1;
    __half* og = ctx + ((size_t)(b * kS + qb + wm + (lane >> 2))) * kDout + h * kHD;
    const int cbase = 2 * (lane & 3);
#pragma unroll
    for (int nt = 0; nt < 8; nt++) {
        const int col = nt * 8 + cbase;
        *(uint32_t*)&og[col] = pack_h2(oacc[nt][0] * inv0, oacc[nt][1] * inv0);
        *(uint32_t*)&og[(size_t)8 * kDout + col] =
            pack_h2(oacc[nt][2] * inv1, oacc[nt][3] * inv1);
    }
}

// ---------------------------------------------------------------------------
extern "C" void kernel_launch(void* const* d_in, const int* in_sizes, int n_in,
                              void* d_out, int out_size)
{
    const float* x  = (const float*)d_in[0];
    const float* Wq = (const float*)d_in[1];
    const float* Wk = (const float*)d_in[2];
    const float* Wv = (const float*)d_in[3];
    const float* Wo = (const float*)d_in[4];

    float* out    = (float*)d_out;
    float* keys   = out + (size_t)kM * kDout;
    float* values = keys + (size_t)kB * kNKV * kS * kHD;

    __half *Qh, *ctxh, *xH, *wH, *woH, *kH, *vH;
    cudaGetSymbolAddress((void**)&Qh,   g_Qh);
    cudaGetSymbolAddress((void**)&ctxh, g_ctxh);
    cudaGetSymbolAddress((void**)&xH,   g_xH);
    cudaGetSymbolAddress((void**)&wH,   g_wH);
    cudaGetSymbolAddress((void**)&woH,  g_woH);
    cudaGetSymbolAddress((void**)&kH,   g_kH);
    cudaGetSymbolAddress((void**)&vH,   g_vH);

    cudaFuncSetAttribute(gemm_f16<0>, cudaFuncAttributeMaxDynamicSharedMemorySize, kGemmSmem);
    cudaFuncSetAttribute(gemm_f16<1>, cudaFuncAttributeMaxDynamicSharedMemorySize, kGemmSmem);
    cudaFuncSetAttribute(attn_mma,    cudaFuncAttributeMaxDynamicSharedMemorySize, kAttSmem);

    // single-pass fp32 -> fp16 conversion
    cvt_all<<<2048, 256>>>((const float4*)x, (const float4*)Wq, (const float4*)Wk,
                           (const float4*)Wv, (const float4*)Wo);

    // fused Q/K/V projection (N = 3072)
    gemm_f16<1><<<dim3(kNQKV / BN, kM / BM), 256, kGemmSmem>>>(
        xH, wH, nullptr, keys, values, kM, kNQKV, kDin);

    // causal GQA attention
    attn_mma<<<dim3(kS / 128, kB * kNH), 256, kAttSmem>>>(Qh, kH, vH, ctxh);

    // output projection
    gemm_f16<0><<<dim3(kDout / BN, kM / BM), 256, kGemmSmem>>>(
        ctxh, woH, out, nullptr, nullptr, kM, kDout, kDin);
}

// round 14
// speedup vs baseline: 1.5145x; 1.5145x over previous
#include <cuda_runtime.h>
#include <cuda_fp16.h>
#include <cstdint>
#include <cstddef>

// ---------------------------------------------------------------------------
// GroupedQueryAttention: B=2, S=2048, D_IN=2048, 32 heads x 64, 8 KV groups
// d_out: out [2,2048,2048] | keys [2,8,2048,64] | values [2,8,2048,64]
// fp16 mma.sync m16n8k16 (fp32 accum) everywhere — measured at the legacy
// HMMA hardware ceiling (~310 TF/s).  This is the R10 configuration (best:
// 427.0 us), re-established after R13's run showed a uniform ~1.5x clock
// artifact (unchanged GEMM kernels slowed 56%).
// ---------------------------------------------------------------------------

namespace {
constexpr int kB    = 2;
constexpr int kS    = 2048;
constexpr int kDin  = 2048;
constexpr int kDout = 2048;
constexpr int kNH   = 32;
constexpr int kNKV  = 8;
constexpr int kHD   = 64;
constexpr int kM    = kB * kS;       // 4096
constexpr int kDkv  = kNKV * kHD;    // 512
constexpr int kNQKV = kDout + 2 * kDkv;   // 3072
constexpr float kQScale = 0.125f * 1.4426950408889634f;   // 1/sqrt(64)*log2(e)
constexpr uint32_t kOnesH2 = 0x3C003C00u;                 // half2(1,1)
}

// Scratch (device globals: no allocation allowed)
__device__ __half g_Qh  [(size_t)kM * kDout];      // pre-scaled fp16 Q
__device__ __half g_ctxh[(size_t)kM * kDout];      // fp16 ctx
__device__ __half g_xH  [(size_t)kM * kDin];
__device__ __half g_wH  [(size_t)kNQKV * kDin];    // [Wq;Wk;Wv] fp16
__device__ __half g_woH [(size_t)kDin * kDout];
__device__ __half g_kH  [(size_t)kB * kNKV * kS * kHD];
__device__ __half g_vH  [(size_t)kB * kNKV * kS * kHD];

// ------------------------- helpers -----------------------------------------
__device__ __forceinline__ uint32_t smem_u32(const void* p) {
    uint32_t a;
    asm("{ .reg .u64 t; cvta.to.shared.u64 t, %1; cvt.u32.u64 %0, t; }" : "=r"(a) : "l"(p));
    return a;
}
__device__ __forceinline__ uint32_t pack_h2(float lo, float hi) {
    uint32_t r;
    asm("cvt.rn.f16x2.f32 %0, %1, %2;" : "=r"(r) : "f"(hi), "f"(lo));
    return r;
}
__device__ __forceinline__ uint32_t h2exp2(uint32_t x) {
    uint32_t r;
    asm("ex2.approx.f16x2 %0, %1;" : "=r"(r) : "r"(x));
    return r;
}
__device__ __forceinline__ float fexp2(float x) {
    float r;
    asm("ex2.approx.f32 %0, %1;" : "=f"(r) : "f"(x));
    return r;
}
// Pure register op: NOT volatile — lets ptxas schedule HMMA freely.
__device__ __forceinline__ void mma_f16(float& c0, float& c1, float& c2, float& c3,
                                        uint32_t a0, uint32_t a1, uint32_t a2, uint32_t a3,
                                        uint32_t b0, uint32_t b1) {
    asm("mma.sync.aligned.m16n8k16.row.col.f32.f16.f16.f32 "
        "{%0,%1,%2,%3}, {%4,%5,%6,%7}, {%8,%9}, {%0,%1,%2,%3};"
        : "+f"(c0), "+f"(c1), "+f"(c2), "+f"(c3)
        : "r"(a0), "r"(a1), "r"(a2), "r"(a3), "r"(b0), "r"(b1));
}
#define LDMX4(r, addr)                                                        \
    asm volatile("ldmatrix.sync.aligned.m8n8.x4.shared.b16 {%0,%1,%2,%3}, [%4];" \
        : "=r"((r)[0]), "=r"((r)[1]), "=r"((r)[2]), "=r"((r)[3]) : "r"(addr))
#define LDMX4T(r, addr)                                                       \
    asm volatile("ldmatrix.sync.aligned.m8n8.x4.trans.shared.b16 {%0,%1,%2,%3}, [%4];" \
        : "=r"((r)[0]), "=r"((r)[1]), "=r"((r)[2]), "=r"((r)[3]) : "r"(addr))
__device__ __forceinline__ void cp_async16(uint32_t dst, const void* src) {
    asm volatile("cp.async.cg.shared.global [%0], [%1], 16;" :: "r"(dst), "l"(src));
}
#define CP_COMMIT() asm volatile("cp.async.commit_group;" ::: "memory")
#define CP_WAIT(n)  asm volatile("cp.async.wait_group %0;" :: "n"(n) : "memory")

// ---------------------------------------------------------------------------
// Single-pass fp32 -> fp16 conversion of x, [Wq;Wk;Wv] and Wo
// ---------------------------------------------------------------------------
namespace {
constexpr int N4X = kM * kDin / 4;
constexpr int N4Q = kDout * kDin / 4;
constexpr int N4K = kDkv * kDin / 4;
constexpr int N4O = kDin * kDout / 4;
constexpr int N4T = N4X + N4Q + 2 * N4K + N4O;
}

__global__ __launch_bounds__(256)
void cvt_all(const float4* __restrict__ x,  const float4* __restrict__ wq,
             const float4* __restrict__ wk, const float4* __restrict__ wv,
             const float4* __restrict__ wo)
{
    uint2* xH  = (uint2*)g_xH;
    uint2* wH  = (uint2*)g_wH;
    uint2* woH = (uint2*)g_woH;
    int i = blockIdx.x * blockDim.x + threadIdx.x;
    const int stride = gridDim.x * blockDim.x;
    for (; i < N4T; i += stride) {
        float4 v;
        uint2* dst;
        if (i < N4X)                       { v = x[i];                       dst = xH + i; }
        else if (i < N4X + N4Q)            { int j = i - N4X;                v = wq[j]; dst = wH + j; }
        else if (i < N4X + N4Q + N4K)      { int j = i - N4X - N4Q;          v = wk[j]; dst = wH + N4Q + j; }
        else if (i < N4X + N4Q + 2 * N4K)  { int j = i - N4X - N4Q - N4K;    v = wv[j]; dst = wH + N4Q + N4K + j; }
        else                               { int j = i - N4X - N4Q - 2*N4K;  v = wo[j]; dst = woH + j; }
        uint2 o;
        o.x = pack_h2(v.x, v.y);
        o.y = pack_h2(v.z, v.w);
        *dst = o;
    }
}

// ---------------------------------------------------------------------------
// GEMM: BM=BN=128, BK=64, 256 threads (8 warps, warp tile 32x64),
// 3-stage cp.async pipeline, one barrier per chunk, grouped raster.
// FUSED: 0 = plain fp32 C (O-proj), 1 = QKV fused epilogue.
// ---------------------------------------------------------------------------
namespace {
constexpr int BM = 128, BN = 128, BK = 64, STR = 72;      // STR in halfs
constexpr int kStageH   = (BM + BN) * STR;                // 18432 halfs
constexpr int kGemmSmem = 3 * kStageH * 2;                // 110592 B
}

template <int FUSED>
__global__ __launch_bounds__(256, 2)
void gemm_f16(const __half* __restrict__ A, const __half* __restrict__ Bw,
              float* __restrict__ C, float* __restrict__ keys,
              float* __restrict__ values, int M, int N, int K)
{
    extern __shared__ __half smh[];
    const uint32_t smBase = smem_u32(smh);

    const int t    = threadIdx.x;
    const int lane = t & 31;
    const int wid  = t >> 5;
    const int wm   = (wid & 3) * 32;
    const int wn   = (wid >> 2) * 64;

    // grouped raster for L2 locality
    const int nbn = gridDim.x, nbm = gridDim.y;
    const int bid = blockIdx.y * nbn + blockIdx.x;
    const int ning = 8 * nbn;
    const int gid  = bid / ning;
    const int fm   = gid * 8;
    const int gsz  = min(8, nbm - fm);
    const int r    = bid % ning;
    const int rowBase = (fm + r % gsz) * BM;
    const int colBase = (r / gsz) * BN;

    float acc[2][8][4] = {};

    auto load_tile = [&](int kt, int st) {
        const __half* Ag = A  + (size_t)rowBase * K + kt * BK;
        const __half* Bg = Bw + (size_t)colBase * K + kt * BK;
        const uint32_t dst = smBase + st * kStageH * 2;
#pragma unroll
        for (int i = 0; i < 4; i++) {
            const int v = t + i * 256;
            const int rr = v >> 3, c8 = (v & 7) * 8;
            cp_async16(dst + (rr * STR + c8) * 2, Ag + (size_t)rr * K + c8);
        }
#pragma unroll
        for (int i = 0; i < 4; i++) {
            const int v = t + i * 256;
            const int rr = v >> 3, c8 = (v & 7) * 8;
            cp_async16(dst + (BM * STR + rr * STR + c8) * 2, Bg + (size_t)rr * K + c8);
        }
        CP_COMMIT();
    };

    const uint32_t aOff = ((wm + (lane & 15)) * STR + (lane >> 4) * 8) * 2;
    const uint32_t bOff = ((wn + ((lane >> 4) & 1) * 8 + (lane & 7)) * STR
                           + ((lane >> 3) & 1) * 8) * 2;

    const int NC = K / BK;
    load_tile(0, 0);
    load_tile(1, 1);

    int st = 0;
    for (int c = 0; c < NC; c++) {
        if (c + 1 < NC) { CP_WAIT(1); } else { CP_WAIT(0); }
        __syncthreads();
        if (c + 2 < NC) {
            int st2 = st + 2; if (st2 >= 3) st2 -= 3;
            load_tile(c + 2, st2);
        }

        const uint32_t ba = smBase + st * kStageH * 2;
        const uint32_t bb = ba + BM * STR * 2;
#pragma unroll
        for (int ks = 0; ks < 4; ks++) {
            uint32_t af[2][4];
            LDMX4(af[0], ba + aOff + (ks * 16) * 2);
            LDMX4(af[1], ba + aOff + (16 * STR + ks * 16) * 2);
#pragma unroll
            for (int p = 0; p < 4; p++) {
                uint32_t bf[4];
                LDMX4(bf, bb + bOff + (p * 16 * STR + ks * 16) * 2);
                mma_f16(acc[0][2*p][0], acc[0][2*p][1], acc[0][2*p][2], acc[0][2*p][3],
                        af[0][0], af[0][1], af[0][2], af[0][3], bf[0], bf[1]);
                mma_f16(acc[1][2*p][0], acc[1][2*p][1], acc[1][2*p][2], acc[1][2*p][3],
                        af[1][0], af[1][1], af[1][2], af[1][3], bf[0], bf[1]);
                mma_f16(acc[0][2*p+1][0], acc[0][2*p+1][1], acc[0][2*p+1][2], acc[0][2*p+1][3],
                        af[0][0], af[0][1], af[0][2], af[0][3], bf[2], bf[3]);
                mma_f16(acc[1][2*p+1][0], acc[1][2*p+1][1], acc[1][2*p+1][2], acc[1][2*p+1][3],
                        af[1][0], af[1][1], af[1][2], af[1][3], bf[2], bf[3]);
            }
        }
        if (++st == 3) st = 0;
    }

    // ---- epilogue
    if (FUSED == 0) {
#pragma unroll
        for (int mt = 0; mt < 2; mt++)
#pragma unroll
        for (int nt = 0; nt < 8; nt++) {
            const int row0 = rowBase + wm + mt * 16 + (lane >> 2);
            const int col  = colBase + wn + nt * 8 + 2 * (lane & 3);
            *(float2*)&C[(size_t)row0 * N + col] =
                make_float2(acc[mt][nt][0], acc[mt][nt][1]);
            *(float2*)&C[(size_t)(row0 + 8) * N + col] =
                make_float2(acc[mt][nt][2], acc[mt][nt][3]);
        }
    } else if (colBase < kDout) {
#pragma unroll
        for (int mt = 0; mt < 2; mt++)
#pragma unroll
        for (int nt = 0; nt < 8; nt++) {
            const int row0 = rowBase + wm + mt * 16 + (lane >> 2);
            const int col  = colBase + wn + nt * 8 + 2 * (lane & 3);
            *(uint32_t*)&g_Qh[(size_t)row0 * kDout + col] =
                pack_h2(kQScale * acc[mt][nt][0], kQScale * acc[mt][nt][1]);
            *(uint32_t*)&g_Qh[(size_t)(row0 + 8) * kDout + col] =
                pack_h2(kQScale * acc[mt][nt][2], kQScale * acc[mt][nt][3]);
        }
    } else {
        const bool isK = colBase < kDout + kDkv;
        float*  d32 = isK ? keys : values;
        __half* d16 = isK ? g_kH : g_vH;
        const int nBase = colBase - (isK ? kDout : (kDout + kDkv));
#pragma unroll
        for (int mt = 0; mt < 2; mt++)
#pragma unroll
        for (int nt = 0; nt < 8; nt++) {
            const int row0 = rowBase + wm + mt * 16 + (lane >> 2);
            const int nloc = nBase + wn + nt * 8 + 2 * (lane & 3);
            const int g = nloc >> 6, d = nloc & 63;
            {
                const int bb2 = row0 >> 11, ss = row0 & (kS - 1);
                const size_t o = ((((size_t)bb2 * kNKV + g) * kS + ss) << 6) + d;
                *(float2*)&d32[o] = make_float2(acc[mt][nt][0], acc[mt][nt][1]);
                *(uint32_t*)&d16[o] = pack_h2(acc[mt][nt][0], acc[mt][nt][1]);
            }
            {
                const int r1 = row0 + 8;
                const int bb2 = r1 >> 11, ss = r1 & (kS - 1);
                const size_t o = ((((size_t)bb2 * kNKV + g) * kS + ss) << 6) + d;
                *(float2*)&d32[o] = make_float2(acc[mt][nt][2], acc[mt][nt][3]);
                *(uint32_t*)&d16[o] = pack_h2(acc[mt][nt][2], acc[mt][nt][3]);
            }
        }
    }
}

// ---------------------------------------------------------------------------
// Causal GQA flash attention, fp16 mma (m16n8k16).
// 8 warps x 16 q-rows = 128 rows/block; 64-key tiles; grid = (S/128, B*NH),
// x reversed so heavy CTAs launch first.  f16x2 exp, ones-mma row sums.
// Double-buffered K/V tiles (R10 configuration).
// ---------------------------------------------------------------------------
namespace {
constexpr int kAStr = 72;
constexpr int kAttBufH = 2 * 64 * kAStr;
constexpr int kAttSmem = 2 * kAttBufH * 2;                 // 36864 B
}

__global__ __launch_bounds__(256, 2)
void attn_mma(const __half* __restrict__ Qh, const __half* __restrict__ KH,
              const __half* __restrict__ VH, __half* __restrict__ ctx)
{
    extern __shared__ __half smh[];
    const uint32_t smBase = smem_u32(smh);

    const int t    = threadIdx.x;
    const int lane = t & 31;
    const int wid  = t >> 5;
    const int bh = blockIdx.y;
    const int b  = bh >> 5;
    const int h  = bh & 31;
    const int g  = h >> 2;
    const int qx = (int)gridDim.x - 1 - (int)blockIdx.x;
    const int qb = qx * 128;
    const int wm = wid * 16;

    const __half* qg = Qh + ((size_t)(b * kS + qb)) * kDout + h * kHD;
#pragma unroll
    for (int i = 0; i < 4; i++) {
        const int v = t + i * 256;
        const int rr = v >> 3, c8 = (v & 7) * 8;
        *(uint4*)&smh[rr * kAStr + c8] = *(const uint4*)&qg[(size_t)rr * kDout + c8];
    }
    __syncthreads();
    uint32_t qf[4][4];
    {
        const uint32_t qOff = smBase + ((wm + (lane & 15)) * kAStr + (lane >> 4) * 8) * 2;
#pragma unroll
        for (int ks = 0; ks < 4; ks++) LDMX4(qf[ks], qOff + (ks * 16) * 2);
    }
    __syncthreads();

    float oacc[8][4] = {};
    float m0 = -1e30f, m1 = -1e30f, l0 = 0.f, l1 = 0.f;

    const __half* kg = KH + ((size_t)(b * kNKV + g)) * kS * kHD;
    const __half* vg = VH + ((size_t)(b * kNKV + g)) * kS * kHD;

    auto load_tile = [&](int kt, int buf) {
        const uint32_t dstK = smBase + buf * kAttBufH * 2;
        const uint32_t dstV = dstK + 64 * kAStr * 2;
#pragma unroll
        for (int i = 0; i < 2; i++) {
            const int v = t + i * 256;
            const int key = v >> 3, c8 = (v & 7) * 8;
            cp_async16(dstK + (key * kAStr + c8) * 2, kg + (size_t)(kt * 64 + key) * kHD + c8);
        }
#pragma unroll
        for (int i = 0; i < 2; i++) {
            const int v = t + i * 256;
            const int key = v >> 3, c8 = (v & 7) * 8;
            cp_async16(dstV + (key * kAStr + c8) * 2, vg + (size_t)(kt * 64 + key) * kHD + c8);
        }
        CP_COMMIT();
    };

    const uint32_t kOffRel =
        ((((lane >> 4) & 1) * 8 + (lane & 7)) * kAStr + ((lane >> 3) & 1) * 8) * 2;
    const uint32_t vOffRel =
        ((((lane >> 3) & 1) * 8 + (lane & 7)) * kAStr + ((lane >> 4) & 1) * 8) * 2;

    const int ntk = qx * 2 + 2;
    load_tile(0, 0);

    for (int kt = 0; kt < ntk; kt++) {
        const int buf = kt & 1;
        if (kt + 1 < ntk) { load_tile(kt + 1, buf ^ 1); CP_WAIT(1); }
        else              { CP_WAIT(0); }
        __syncthreads();

        if (kt * 64 <= qb + wm + 15) {
            const uint32_t kBase = smBase + buf * kAttBufH * 2 + kOffRel;
            const uint32_t vBase = smBase + buf * kAttBufH * 2 + 64 * kAStr * 2 + vOffRel;

            float sacc[8][4] = {};
#pragma unroll
            for (int ks = 0; ks < 4; ks++) {
#pragma unroll
                for (int p = 0; p < 4; p++) {
                    uint32_t bf[4];
                    LDMX4(bf, kBase + (p * 16 * kAStr + ks * 16) * 2);
                    mma_f16(sacc[2*p][0], sacc[2*p][1], sacc[2*p][2], sacc[2*p][3],
                            qf[ks][0], qf[ks][1], qf[ks][2], qf[ks][3], bf[0], bf[1]);
                    mma_f16(sacc[2*p+1][0], sacc[2*p+1][1], sacc[2*p+1][2], sacc[2*p+1][3],
                            qf[ks][0], qf[ks][1], qf[ks][2], qf[ks][3], bf[2], bf[3]);
                }
            }

            const int r0 = qb + wm + (lane >> 2);
            const int r1 = r0 + 8;
            if (kt * 64 + 63 > qb + wm) {
#pragma unroll
                for (int nt = 0; nt < 8; nt++) {
                    const int c0 = kt * 64 + nt * 8 + 2 * (lane & 3);
                    if (c0     > r0) sacc[nt][0] = -1e30f;
                    if (c0 + 1 > r0) sacc[nt][1] = -1e30f;
                    if (c0     > r1) sacc[nt][2] = -1e30f;
                    if (c0 + 1 > r1) sacc[nt][3] = -1e30f;
                }
            }

            float t0 = -1e30f, t1 = -1e30f;
#pragma unroll
            for (int nt = 0; nt < 8; nt++) {
                t0 = fmaxf(t0, fmaxf(sacc[nt][0], sacc[nt][1]));
                t1 = fmaxf(t1, fmaxf(sacc[nt][2], sacc[nt][3]));
            }
            t0 = fmaxf(t0, __shfl_xor_sync(0xFFFFFFFFu, t0, 1));
            t0 = fmaxf(t0, __shfl_xor_sync(0xFFFFFFFFu, t0, 2));
            t1 = fmaxf(t1, __shfl_xor_sync(0xFFFFFFFFu, t1, 1));
            t1 = fmaxf(t1, __shfl_xor_sync(0xFFFFFFFFu, t1, 2));
            const float mn0 = fmaxf(m0, t0);
            const float mn1 = fmaxf(m1, t1);
            const float corr0 = fexp2(m0 - mn0);
            const float corr1 = fexp2(m1 - mn1);
            m0 = mn0; m1 = mn1;

            uint32_t p01[8], p23[8];
#pragma unroll
            for (int nt = 0; nt < 8; nt++) {
                p01[nt] = h2exp2(pack_h2(sacc[nt][0] - mn0, sacc[nt][1] - mn0));
                p23[nt] = h2exp2(pack_h2(sacc[nt][2] - mn1, sacc[nt][3] - mn1));
            }

#pragma unroll
            for (int nt = 0; nt < 8; nt++) {
                oacc[nt][0] *= corr0; oacc[nt][1] *= corr0;
                oacc[nt][2] *= corr1; oacc[nt][3] *= corr1;
            }

            float lacc[4] = {};
#pragma unroll
            for (int ks = 0; ks < 4; ks++) {
                const uint32_t a0 = p01[2*ks];
                const uint32_t a1 = p23[2*ks];
                const uint32_t a2 = p01[2*ks+1];
                const uint32_t a3 = p23[2*ks+1];
                mma_f16(lacc[0], lacc[1], lacc[2], lacc[3],
                        a0, a1, a2, a3, kOnesH2, kOnesH2);
#pragma unroll
                for (int p = 0; p < 4; p++) {
                    uint32_t vf[4];
                    LDMX4T(vf, vBase + (ks * 16 * kAStr + p * 16) * 2);
                    mma_f16(oacc[2*p][0], oacc[2*p][1], oacc[2*p][2], oacc[2*p][3],
                            a0, a1, a2, a3, vf[0], vf[1]);
                    mma_f16(oacc[2*p+1][0], oacc[2*p+1][1], oacc[2*p+1][2], oacc[2*p+1][3],
                            a0, a1, a2, a3, vf[2], vf[3]);
                }
            }
            l0 = l0 * corr0 + lacc[0];
            l1 = l1 * corr1 + lacc[2];
        }
        __syncthreads();
    }

    const float inv0 = 1.f / l0;
    const float inv1 = 1.f / l1;
    __half* og = ctx + ((size_t)(b * kS + qb + wm + (lane >> 2))) * kDout + h * kHD;
    const int cbase = 2 * (lane & 3);
#pragma unroll
    for (int nt = 0; nt < 8; nt++) {
        const int col = nt * 8 + cbase;
        *(uint32_t*)&og[col] = pack_h2(oacc[nt][0] * inv0, oacc[nt][1] * inv0);
        *(uint32_t*)&og[(size_t)8 * kDout + col] =
            pack_h2(oacc[nt][2] * inv1, oacc[nt][3] * inv1);
    }
}

// ---------------------------------------------------------------------------
extern "C" void kernel_launch(void* const* d_in, const int* in_sizes, int n_in,
                              void* d_out, int out_size)
{
    const float* x  = (const float*)d_in[0];
    const float* Wq = (const float*)d_in[1];
    const float* Wk = (const float*)d_in[2];
    const float* Wv = (const float*)d_in[3];
    const float* Wo = (const float*)d_in[4];

    float* out    = (float*)d_out;
    float* keys   = out + (size_t)kM * kDout;
    float* values = keys + (size_t)kB * kNKV * kS * kHD;

    __half *Qh, *ctxh, *xH, *wH, *woH, *kH, *vH;
    cudaGetSymbolAddress((void**)&Qh,   g_Qh);
    cudaGetSymbolAddress((void**)&ctxh, g_ctxh);
    cudaGetSymbolAddress((void**)&xH,   g_xH);
    cudaGetSymbolAddress((void**)&wH,   g_wH);
    cudaGetSymbolAddress((void**)&woH,  g_woH);
    cudaGetSymbolAddress((void**)&kH,   g_kH);
    cudaGetSymbolAddress((void**)&vH,   g_vH);

    cudaFuncSetAttribute(gemm_f16<0>, cudaFuncAttributeMaxDynamicSharedMemorySize, kGemmSmem);
    cudaFuncSetAttribute(gemm_f16<1>, cudaFuncAttributeMaxDynamicSharedMemorySize, kGemmSmem);
    cudaFuncSetAttribute(attn_mma,    cudaFuncAttributeMaxDynamicSharedMemorySize, kAttSmem);

    // single-pass fp32 -> fp16 conversion
    cvt_all<<<2048, 256>>>((const float4*)x, (const float4*)Wq, (const float4*)Wk,
                           (const float4*)Wv, (const float4*)Wo);

    // fused Q/K/V projection (N = 3072)
    gemm_f16<1><<<dim3(kNQKV / BN, kM / BM), 256, kGemmSmem>>>(
        xH, wH, nullptr, keys, values, kM, kNQKV, kDin);

    // causal GQA attention
    attn_mma<<<dim3(kS / 128, kB * kNH), 256, kAttSmem>>>(Qh, kH, vH, ctxh);

    // output projection
    gemm_f16<0><<<dim3(kDout / BN, kM / BM), 256, kGemmSmem>>>(
        ctxh, woH, out, nullptr, nullptr, kM, kDout, kDin);
}

// round 15
// speedup vs baseline: 1.5192x; 1.0032x over previous
#include <cuda_runtime.h>
#include <cuda_fp16.h>
#include <cstdint>
#include <cstddef>

// ---------------------------------------------------------------------------
// GroupedQueryAttention: B=2, S=2048, D_IN=2048, 32 heads x 64, 8 KV groups
// d_out: out [2,2048,2048] | keys [2,8,2048,64] | values [2,8,2048,64]
// fp16 mma.sync m16n8k16 (fp32 accum) everywhere.
// FINAL (R10 config): measured at the sm_103 legacy-HMMA hardware ceiling —
// rt=16 cyc/HMMA/SMSP => ~309 TF/s; QKV 167us + attn 140us + O-proj 111us +
// cvt ~12us are each at 97-100% of that roofline. tcgen05 (the faster path)
// is unavailable under the compute_103 virtual arch this bench compiles with.
// ---------------------------------------------------------------------------

namespace {
constexpr int kB    = 2;
constexpr int kS    = 2048;
constexpr int kDin  = 2048;
constexpr int kDout = 2048;
constexpr int kNH   = 32;
constexpr int kNKV  = 8;
constexpr int kHD   = 64;
constexpr int kM    = kB * kS;       // 4096
constexpr int kDkv  = kNKV * kHD;    // 512
constexpr int kNQKV = kDout + 2 * kDkv;   // 3072
constexpr float kQScale = 0.125f * 1.4426950408889634f;   // 1/sqrt(64)*log2(e)
constexpr uint32_t kOnesH2 = 0x3C003C00u;                 // half2(1,1)
}

// Scratch (device globals: no allocation allowed)
__device__ __half g_Qh  [(size_t)kM * kDout];      // pre-scaled fp16 Q
__device__ __half g_ctxh[(size_t)kM * kDout];      // fp16 ctx
__device__ __half g_xH  [(size_t)kM * kDin];
__device__ __half g_wH  [(size_t)kNQKV * kDin];    // [Wq;Wk;Wv] fp16
__device__ __half g_woH [(size_t)kDin * kDout];
__device__ __half g_kH  [(size_t)kB * kNKV * kS * kHD];
__device__ __half g_vH  [(size_t)kB * kNKV * kS * kHD];

// ------------------------- helpers -----------------------------------------
__device__ __forceinline__ uint32_t smem_u32(const void* p) {
    uint32_t a;
    asm("{ .reg .u64 t; cvta.to.shared.u64 t, %1; cvt.u32.u64 %0, t; }" : "=r"(a) : "l"(p));
    return a;
}
__device__ __forceinline__ uint32_t pack_h2(float lo, float hi) {
    uint32_t r;
    asm("cvt.rn.f16x2.f32 %0, %1, %2;" : "=r"(r) : "f"(hi), "f"(lo));
    return r;
}
__device__ __forceinline__ uint32_t h2exp2(uint32_t x) {
    uint32_t r;
    asm("ex2.approx.f16x2 %0, %1;" : "=r"(r) : "r"(x));
    return r;
}
__device__ __forceinline__ float fexp2(float x) {
    float r;
    asm("ex2.approx.f32 %0, %1;" : "=f"(r) : "f"(x));
    return r;
}
// Pure register op: NOT volatile — lets ptxas schedule HMMA freely.
__device__ __forceinline__ void mma_f16(float& c0, float& c1, float& c2, float& c3,
                                        uint32_t a0, uint32_t a1, uint32_t a2, uint32_t a3,
                                        uint32_t b0, uint32_t b1) {
    asm("mma.sync.aligned.m16n8k16.row.col.f32.f16.f16.f32 "
        "{%0,%1,%2,%3}, {%4,%5,%6,%7}, {%8,%9}, {%0,%1,%2,%3};"
        : "+f"(c0), "+f"(c1), "+f"(c2), "+f"(c3)
        : "r"(a0), "r"(a1), "r"(a2), "r"(a3), "r"(b0), "r"(b1));
}
#define LDMX4(r, addr)                                                        \
    asm volatile("ldmatrix.sync.aligned.m8n8.x4.shared.b16 {%0,%1,%2,%3}, [%4];" \
        : "=r"((r)[0]), "=r"((r)[1]), "=r"((r)[2]), "=r"((r)[3]) : "r"(addr))
#define LDMX4T(r, addr)                                                       \
    asm volatile("ldmatrix.sync.aligned.m8n8.x4.trans.shared.b16 {%0,%1,%2,%3}, [%4];" \
        : "=r"((r)[0]), "=r"((r)[1]), "=r"((r)[2]), "=r"((r)[3]) : "r"(addr))
__device__ __forceinline__ void cp_async16(uint32_t dst, const void* src) {
    asm volatile("cp.async.cg.shared.global [%0], [%1], 16;" :: "r"(dst), "l"(src));
}
#define CP_COMMIT() asm volatile("cp.async.commit_group;" ::: "memory")
#define CP_WAIT(n)  asm volatile("cp.async.wait_group %0;" :: "n"(n) : "memory")

// ---------------------------------------------------------------------------
// Single-pass fp32 -> fp16 conversion of x, [Wq;Wk;Wv] and Wo
// ---------------------------------------------------------------------------
namespace {
constexpr int N4X = kM * kDin / 4;
constexpr int N4Q = kDout * kDin / 4;
constexpr int N4K = kDkv * kDin / 4;
constexpr int N4O = kDin * kDout / 4;
constexpr int N4T = N4X + N4Q + 2 * N4K + N4O;
}

__global__ __launch_bounds__(256)
void cvt_all(const float4* __restrict__ x,  const float4* __restrict__ wq,
             const float4* __restrict__ wk, const float4* __restrict__ wv,
             const float4* __restrict__ wo)
{
    uint2* xH  = (uint2*)g_xH;
    uint2* wH  = (uint2*)g_wH;
    uint2* woH = (uint2*)g_woH;
    int i = blockIdx.x * blockDim.x + threadIdx.x;
    const int stride = gridDim.x * blockDim.x;
    for (; i < N4T; i += stride) {
        float4 v;
        uint2* dst;
        if (i < N4X)                       { v = x[i];                       dst = xH + i; }
        else if (i < N4X + N4Q)            { int j = i - N4X;                v = wq[j]; dst = wH + j; }
        else if (i < N4X + N4Q + N4K)      { int j = i - N4X - N4Q;          v = wk[j]; dst = wH + N4Q + j; }
        else if (i < N4X + N4Q + 2 * N4K)  { int j = i - N4X - N4Q - N4K;    v = wv[j]; dst = wH + N4Q + N4K + j; }
        else                               { int j = i - N4X - N4Q - 2*N4K;  v = wo[j]; dst = woH + j; }
        uint2 o;
        o.x = pack_h2(v.x, v.y);
        o.y = pack_h2(v.z, v.w);
        *dst = o;
    }
}

// ---------------------------------------------------------------------------
// GEMM: BM=BN=128, BK=64, 256 threads (8 warps, warp tile 32x64),
// 3-stage cp.async pipeline, one barrier per chunk, grouped raster.
// FUSED: 0 = plain fp32 C (O-proj), 1 = QKV fused epilogue.
// ---------------------------------------------------------------------------
namespace {
constexpr int BM = 128, BN = 128, BK = 64, STR = 72;      // STR in halfs
constexpr int kStageH   = (BM + BN) * STR;                // 18432 halfs
constexpr int kGemmSmem = 3 * kStageH * 2;                // 110592 B
}

template <int FUSED>
__global__ __launch_bounds__(256, 2)
void gemm_f16(const __half* __restrict__ A, const __half* __restrict__ Bw,
              float* __restrict__ C, float* __restrict__ keys,
              float* __restrict__ values, int M, int N, int K)
{
    extern __shared__ __half smh[];
    const uint32_t smBase = smem_u32(smh);

    const int t    = threadIdx.x;
    const int lane = t & 31;
    const int wid  = t >> 5;
    const int wm   = (wid & 3) * 32;
    const int wn   = (wid >> 2) * 64;

    // grouped raster for L2 locality
    const int nbn = gridDim.x, nbm = gridDim.y;
    const int bid = blockIdx.y * nbn + blockIdx.x;
    const int ning = 8 * nbn;
    const int gid  = bid / ning;
    const int fm   = gid * 8;
    const int gsz  = min(8, nbm - fm);
    const int r    = bid % ning;
    const int rowBase = (fm + r % gsz) * BM;
    const int colBase = (r / gsz) * BN;

    float acc[2][8][4] = {};

    auto load_tile = [&](int kt, int st) {
        const __half* Ag = A  + (size_t)rowBase * K + kt * BK;
        const __half* Bg = Bw + (size_t)colBase * K + kt * BK;
        const uint32_t dst = smBase + st * kStageH * 2;
#pragma unroll
        for (int i = 0; i < 4; i++) {
            const int v = t + i * 256;
            const int rr = v >> 3, c8 = (v & 7) * 8;
            cp_async16(dst + (rr * STR + c8) * 2, Ag + (size_t)rr * K + c8);
        }
#pragma unroll
        for (int i = 0; i < 4; i++) {
            const int v = t + i * 256;
            const int rr = v >> 3, c8 = (v & 7) * 8;
            cp_async16(dst + (BM * STR + rr * STR + c8) * 2, Bg + (size_t)rr * K + c8);
        }
        CP_COMMIT();
    };

    const uint32_t aOff = ((wm + (lane & 15)) * STR + (lane >> 4) * 8) * 2;
    const uint32_t bOff = ((wn + ((lane >> 4) & 1) * 8 + (lane & 7)) * STR
                           + ((lane >> 3) & 1) * 8) * 2;

    const int NC = K / BK;
    load_tile(0, 0);
    load_tile(1, 1);

    int st = 0;
    for (int c = 0; c < NC; c++) {
        if (c + 1 < NC) { CP_WAIT(1); } else { CP_WAIT(0); }
        __syncthreads();
        if (c + 2 < NC) {
            int st2 = st + 2; if (st2 >= 3) st2 -= 3;
            load_tile(c + 2, st2);
        }

        const uint32_t ba = smBase + st * kStageH * 2;
        const uint32_t bb = ba + BM * STR * 2;
#pragma unroll
        for (int ks = 0; ks < 4; ks++) {
            uint32_t af[2][4];
            LDMX4(af[0], ba + aOff + (ks * 16) * 2);
            LDMX4(af[1], ba + aOff + (16 * STR + ks * 16) * 2);
#pragma unroll
            for (int p = 0; p < 4; p++) {
                uint32_t bf[4];
                LDMX4(bf, bb + bOff + (p * 16 * STR + ks * 16) * 2);
                mma_f16(acc[0][2*p][0], acc[0][2*p][1], acc[0][2*p][2], acc[0][2*p][3],
                        af[0][0], af[0][1], af[0][2], af[0][3], bf[0], bf[1]);
                mma_f16(acc[1][2*p][0], acc[1][2*p][1], acc[1][2*p][2], acc[1][2*p][3],
                        af[1][0], af[1][1], af[1][2], af[1][3], bf[0], bf[1]);
                mma_f16(acc[0][2*p+1][0], acc[0][2*p+1][1], acc[0][2*p+1][2], acc[0][2*p+1][3],
                        af[0][0], af[0][1], af[0][2], af[0][3], bf[2], bf[3]);
                mma_f16(acc[1][2*p+1][0], acc[1][2*p+1][1], acc[1][2*p+1][2], acc[1][2*p+1][3],
                        af[1][0], af[1][1], af[1][2], af[1][3], bf[2], bf[3]);
            }
        }
        if (++st == 3) st = 0;
    }

    // ---- epilogue
    if (FUSED == 0) {
#pragma unroll
        for (int mt = 0; mt < 2; mt++)
#pragma unroll
        for (int nt = 0; nt < 8; nt++) {
            const int row0 = rowBase + wm + mt * 16 + (lane >> 2);
            const int col  = colBase + wn + nt * 8 + 2 * (lane & 3);
            *(float2*)&C[(size_t)row0 * N + col] =
                make_float2(acc[mt][nt][0], acc[mt][nt][1]);
            *(float2*)&C[(size_t)(row0 + 8) * N + col] =
                make_float2(acc[mt][nt][2], acc[mt][nt][3]);
        }
    } else if (colBase < kDout) {
#pragma unroll
        for (int mt = 0; mt < 2; mt++)
#pragma unroll
        for (int nt = 0; nt < 8; nt++) {
            const int row0 = rowBase + wm + mt * 16 + (lane >> 2);
            const int col  = colBase + wn + nt * 8 + 2 * (lane & 3);
            *(uint32_t*)&g_Qh[(size_t)row0 * kDout + col] =
                pack_h2(kQScale * acc[mt][nt][0], kQScale * acc[mt][nt][1]);
            *(uint32_t*)&g_Qh[(size_t)(row0 + 8) * kDout + col] =
                pack_h2(kQScale * acc[mt][nt][2], kQScale * acc[mt][nt][3]);
        }
    } else {
        const bool isK = colBase < kDout + kDkv;
        float*  d32 = isK ? keys : values;
        __half* d16 = isK ? g_kH : g_vH;
        const int nBase = colBase - (isK ? kDout : (kDout + kDkv));
#pragma unroll
        for (int mt = 0; mt < 2; mt++)
#pragma unroll
        for (int nt = 0; nt < 8; nt++) {
            const int row0 = rowBase + wm + mt * 16 + (lane >> 2);
            const int nloc = nBase + wn + nt * 8 + 2 * (lane & 3);
            const int g = nloc >> 6, d = nloc & 63;
            {
                const int bb2 = row0 >> 11, ss = row0 & (kS - 1);
                const size_t o = ((((size_t)bb2 * kNKV + g) * kS + ss) << 6) + d;
                *(float2*)&d32[o] = make_float2(acc[mt][nt][0], acc[mt][nt][1]);
                *(uint32_t*)&d16[o] = pack_h2(acc[mt][nt][0], acc[mt][nt][1]);
            }
            {
                const int r1 = row0 + 8;
                const int bb2 = r1 >> 11, ss = r1 & (kS - 1);
                const size_t o = ((((size_t)bb2 * kNKV + g) * kS + ss) << 6) + d;
                *(float2*)&d32[o] = make_float2(acc[mt][nt][2], acc[mt][nt][3]);
                *(uint32_t*)&d16[o] = pack_h2(acc[mt][nt][2], acc[mt][nt][3]);
            }
        }
    }
}

// ---------------------------------------------------------------------------
// Causal GQA flash attention, fp16 mma (m16n8k16).
// 8 warps x 16 q-rows = 128 rows/block; 64-key tiles; grid = (S/128, B*NH),
// x reversed so heavy CTAs launch first.  f16x2 exp, ones-mma row sums.
// Double-buffered K/V tiles.
// ---------------------------------------------------------------------------
namespace {
constexpr int kAStr = 72;
constexpr int kAttBufH = 2 * 64 * kAStr;
constexpr int kAttSmem = 2 * kAttBufH * 2;                 // 36864 B
}

__global__ __launch_bounds__(256, 2)
void attn_mma(const __half* __restrict__ Qh, const __half* __restrict__ KH,
              const __half* __restrict__ VH, __half* __restrict__ ctx)
{
    extern __shared__ __half smh[];
    const uint32_t smBase = smem_u32(smh);

    const int t    = threadIdx.x;
    const int lane = t & 31;
    const int wid  = t >> 5;
    const int bh = blockIdx.y;
    const int b  = bh >> 5;
    const int h  = bh & 31;
    const int g  = h >> 2;
    const int qx = (int)gridDim.x - 1 - (int)blockIdx.x;
    const int qb = qx * 128;
    const int wm = wid * 16;

    const __half* qg = Qh + ((size_t)(b * kS + qb)) * kDout + h * kHD;
#pragma unroll
    for (int i = 0; i < 4; i++) {
        const int v = t + i * 256;
        const int rr = v >> 3, c8 = (v & 7) * 8;
        *(uint4*)&smh[rr * kAStr + c8] = *(const uint4*)&qg[(size_t)rr * kDout + c8];
    }
    __syncthreads();
    uint32_t qf[4][4];
    {
        const uint32_t qOff = smBase + ((wm + (lane & 15)) * kAStr + (lane >> 4) * 8) * 2;
#pragma unroll
        for (int ks = 0; ks < 4; ks++) LDMX4(qf[ks], qOff + (ks * 16) * 2);
    }
    __syncthreads();

    float oacc[8][4] = {};
    float m0 = -1e30f, m1 = -1e30f, l0 = 0.f, l1 = 0.f;

    const __half* kg = KH + ((size_t)(b * kNKV + g)) * kS * kHD;
    const __half* vg = VH + ((size_t)(b * kNKV + g)) * kS * kHD;

    auto load_tile = [&](int kt, int buf) {
        const uint32_t dstK = smBase + buf * kAttBufH * 2;
        const uint32_t dstV = dstK + 64 * kAStr * 2;
#pragma unroll
        for (int i = 0; i < 2; i++) {
            const int v = t + i * 256;
            const int key = v >> 3, c8 = (v & 7) * 8;
            cp_async16(dstK + (key * kAStr + c8) * 2, kg + (size_t)(kt * 64 + key) * kHD + c8);
        }
#pragma unroll
        for (int i = 0; i < 2; i++) {
            const int v = t + i * 256;
            const int key = v >> 3, c8 = (v & 7) * 8;
            cp_async16(dstV + (key * kAStr + c8) * 2, vg + (size_t)(kt * 64 + key) * kHD + c8);
        }
        CP_COMMIT();
    };

    const uint32_t kOffRel =
        ((((lane >> 4) & 1) * 8 + (lane & 7)) * kAStr + ((lane >> 3) & 1) * 8) * 2;
    const uint32_t vOffRel =
        ((((lane >> 3) & 1) * 8 + (lane & 7)) * kAStr + ((lane >> 4) & 1) * 8) * 2;

    const int ntk = qx * 2 + 2;
    load_tile(0, 0);

    for (int kt = 0; kt < ntk; kt++) {
        const int buf = kt & 1;
        if (kt + 1 < ntk) { load_tile(kt + 1, buf ^ 1); CP_WAIT(1); }
        else              { CP_WAIT(0); }
        __syncthreads();

        if (kt * 64 <= qb + wm + 15) {
            const uint32_t kBase = smBase + buf * kAttBufH * 2 + kOffRel;
            const uint32_t vBase = smBase + buf * kAttBufH * 2 + 64 * kAStr * 2 + vOffRel;

            float sacc[8][4] = {};
#pragma unroll
            for (int ks = 0; ks < 4; ks++) {
#pragma unroll
                for (int p = 0; p < 4; p++) {
                    uint32_t bf[4];
                    LDMX4(bf, kBase + (p * 16 * kAStr + ks * 16) * 2);
                    mma_f16(sacc[2*p][0], sacc[2*p][1], sacc[2*p][2], sacc[2*p][3],
                            qf[ks][0], qf[ks][1], qf[ks][2], qf[ks][3], bf[0], bf[1]);
                    mma_f16(sacc[2*p+1][0], sacc[2*p+1][1], sacc[2*p+1][2], sacc[2*p+1][3],
                            qf[ks][0], qf[ks][1], qf[ks][2], qf[ks][3], bf[2], bf[3]);
                }
            }

            const int r0 = qb + wm + (lane >> 2);
            const int r1 = r0 + 8;
            if (kt * 64 + 63 > qb + wm) {
#pragma unroll
                for (int nt = 0; nt < 8; nt++) {
                    const int c0 = kt * 64 + nt * 8 + 2 * (lane & 3);
                    if (c0     > r0) sacc[nt][0] = -1e30f;
                    if (c0 + 1 > r0) sacc[nt][1] = -1e30f;
                    if (c0     > r1) sacc[nt][2] = -1e30f;
                    if (c0 + 1 > r1) sacc[nt][3] = -1e30f;
                }
            }

            float t0 = -1e30f, t1 = -1e30f;
#pragma unroll
            for (int nt = 0; nt < 8; nt++) {
                t0 = fmaxf(t0, fmaxf(sacc[nt][0], sacc[nt][1]));
                t1 = fmaxf(t1, fmaxf(sacc[nt][2], sacc[nt][3]));
            }
            t0 = fmaxf(t0, __shfl_xor_sync(0xFFFFFFFFu, t0, 1));
            t0 = fmaxf(t0, __shfl_xor_sync(0xFFFFFFFFu, t0, 2));
            t1 = fmaxf(t1, __shfl_xor_sync(0xFFFFFFFFu, t1, 1));
            t1 = fmaxf(t1, __shfl_xor_sync(0xFFFFFFFFu, t1, 2));
            const float mn0 = fmaxf(m0, t0);
            const float mn1 = fmaxf(m1, t1);
            const float corr0 = fexp2(m0 - mn0);
            const float corr1 = fexp2(m1 - mn1);
            m0 = mn0; m1 = mn1;

            uint32_t p01[8], p23[8];
#pragma unroll
            for (int nt = 0; nt < 8; nt++) {
                p01[nt] = h2exp2(pack_h2(sacc[nt][0] - mn0, sacc[nt][1] - mn0));
                p23[nt] = h2exp2(pack_h2(sacc[nt][2] - mn1, sacc[nt][3] - mn1));
            }

#pragma unroll
            for (int nt = 0; nt < 8; nt++) {
                oacc[nt][0] *= corr0; oacc[nt][1] *= corr0;
                oacc[nt][2] *= corr1; oacc[nt][3] *= corr1;
            }

            float lacc[4] = {};
#pragma unroll
            for (int ks = 0; ks < 4; ks++) {
                const uint32_t a0 = p01[2*ks];
                const uint32_t a1 = p23[2*ks];
                const uint32_t a2 = p01[2*ks+1];
                const uint32_t a3 = p23[2*ks+1];
                mma_f16(lacc[0], lacc[1], lacc[2], lacc[3],
                        a0, a1, a2, a3, kOnesH2, kOnesH2);
#pragma unroll
                for (int p = 0; p < 4; p++) {
                    uint32_t vf[4];
                    LDMX4T(vf, vBase + (ks * 16 * kAStr + p * 16) * 2);
                    mma_f16(oacc[2*p][0], oacc[2*p][1], oacc[2*p][2], oacc[2*p][3],
                            a0, a1, a2, a3, vf[0], vf[1]);
                    mma_f16(oacc[2*p+1][0], oacc[2*p+1][1], oacc[2*p+1][2], oacc[2*p+1][3],
                            a0, a1, a2, a3, vf[2], vf[3]);
                }
            }
            l0 = l0 * corr0 + lacc[0];
            l1 = l1 * corr1 + lacc[2];
        }
        __syncthreads();
    }

    const float inv0 = 1.f / l0;
    const float inv1 = 1.f / l1;
    __half* og = ctx + ((size_t)(b * kS + qb + wm + (lane >> 2))) * kDout + h * kHD;
    const int cbase = 2 * (lane & 3);
#pragma unroll
    for (int nt = 0; nt < 8; nt++) {
        const int col = nt * 8 + cbase;
        *(uint32_t*)&og[col] = pack_h2(oacc[nt][0] * inv0, oacc[nt][1] * inv0);
        *(uint32_t*)&og[(size_t)8 * kDout + col] =
            pack_h2(oacc[nt][2] * inv1, oacc[nt][3] * inv1);
    }
}

// ---------------------------------------------------------------------------
extern "C" void kernel_launch(void* const* d_in, const int* in_sizes, int n_in,
                              void* d_out, int out_size)
{
    const float* x  = (const float*)d_in[0];
    const float* Wq = (const float*)d_in[1];
    const float* Wk = (const float*)d_in[2];
    const float* Wv = (const float*)d_in[3];
    const float* Wo = (const float*)d_in[4];

    float* out    = (float*)d_out;
    float* keys   = out + (size_t)kM * kDout;
    float* values = keys + (size_t)kB * kNKV * kS * kHD;

    __half *Qh, *ctxh, *xH, *wH, *woH, *kH, *vH;
    cudaGetSymbolAddress((void**)&Qh,   g_Qh);
    cudaGetSymbolAddress((void**)&ctxh, g_ctxh);
    cudaGetSymbolAddress((void**)&xH,   g_xH);
    cudaGetSymbolAddress((void**)&wH,   g_wH);
    cudaGetSymbolAddress((void**)&woH,  g_woH);
    cudaGetSymbolAddress((void**)&kH,   g_kH);
    cudaGetSymbolAddress((void**)&vH,   g_vH);

    cudaFuncSetAttribute(gemm_f16<0>, cudaFuncAttributeMaxDynamicSharedMemorySize, kGemmSmem);
    cudaFuncSetAttribute(gemm_f16<1>, cudaFuncAttributeMaxDynamicSharedMemorySize, kGemmSmem);
    cudaFuncSetAttribute(attn_mma,    cudaFuncAttributeMaxDynamicSharedMemorySize, kAttSmem);

    // single-pass fp32 -> fp16 conversion
    cvt_all<<<2048, 256>>>((const float4*)x, (const float4*)Wq, (const float4*)Wk,
                           (const float4*)Wv, (const float4*)Wo);

    // fused Q/K/V projection (N = 3072)
    gemm_f16<1><<<dim3(kNQKV / BN, kM / BM), 256, kGemmSmem>>>(
        xH, wH, nullptr, keys, values, kM, kNQKV, kDin);

    // causal GQA attention
    attn_mma<<<dim3(kS / 128, kB * kNH), 256, kAttSmem>>>(Qh, kH, vH, ctxh);

    // output projection
    gemm_f16<0><<<dim3(kDout / BN, kM / BM), 256, kGemmSmem>>>(
        ctxh, woH, out, nullptr, nullptr, kM, kDout, kDin);
}